// round 12
// baseline (speedup 1.0000x reference)
#include <cuda_runtime.h>
#include <cuda_bf16.h>
#include <math.h>
#include <stdint.h>

#define N_TOK   65536
#define DIM     256
#define KCODES  1024
#define LAYERS  8
#define THREADS 256
#define TOKB    64            // tokens per CTA
#define NT_TILES 256          // 8 layers * 8 nchunks * 4 dchunks
#define BROW    80            // B smem row bytes: 64 int8 + 16 pad
#define BSTAGE  (128*BROW)    // 10240 B per stage
#define NSTAGE  3
#define AROWB   272           // A smem row bytes: 256 int8 + 16 pad
#define AROWU   68            // A row stride in u32

// smem byte offsets
#define SM_AH    0
#define SM_B     (SM_AH + TOKB*AROWB)         // 17408
#define SM_SE    (SM_B + NSTAGE*BSTAGE)       // 48128
#define SM_ZSQ   (SM_SE + 4096)               // 52224
#define SM_SR    (SM_ZSQ + 256)               // 52480
#define SM_MAR   (SM_SR + 256)                // 52736
#define SM_GMIN  (SM_MAR + 256)               // 52992
#define SM_GM2   (SM_GMIN + 256)              // 53248  f32[64][4]
#define SM_CCNT  (SM_GM2 + 1024)              // 54272
#define SM_FULL  (SM_CCNT + 256)              // 54528
#define SM_CAND  (SM_FULL + 256)              // 54784  u16[64][64]
#define SM_BEST  (SM_CAND + 8192)             // 62976  u64[64]
#define SM_IDX   (SM_BEST + 512)              // 63488
#define SM_FLAG  (SM_IDX + 256)               // 63744
#define SM_NFL   (SM_FLAG + 256)              // 64000
#define SM_TOTAL (SM_NFL + 16)                // 64016

// ---------------- device globals ----------------
__device__ double        g_loss[LAYERS];
__device__ unsigned int  g_counts[LAYERS * KCODES];
__device__ float         g_esq[LAYERS * KCODES];
__device__ unsigned int  g_cmaxb[LAYERS];     // max ||c|| per layer (float bits)
__device__ unsigned int  g_clomaxb[LAYERS];   // max ||c - sc*q_c|| per layer
__device__ unsigned int  g_cabsmax[LAYERS];   // max |c| per layer (float bits)
__device__ uint4         g_cbq[LAYERS * KCODES * (DIM/16)];   // int8 codebooks
__device__ float         g_resid[(size_t)N_TOK * DIM];        // EXACT fp32 residual

// ---------------- helpers ----------------
__device__ __forceinline__ uint32_t smem_u32p(const void* p) {
    uint32_t a;
    asm("{ .reg .u64 t; cvta.to.shared.u64 t, %1; cvt.u32.u64 %0, t; }" : "=r"(a) : "l"(p));
    return a;
}
__device__ __forceinline__ void ldsm_x4(uint32_t* r, uint32_t addr) {
    asm volatile("ldmatrix.sync.aligned.m8n8.x4.shared.b16 {%0,%1,%2,%3}, [%4];"
        : "=r"(r[0]), "=r"(r[1]), "=r"(r[2]), "=r"(r[3]) : "r"(addr));
}
__device__ __forceinline__ void mma_i8(int* c, const uint32_t* a, uint32_t b0, uint32_t b1) {
    asm volatile("mma.sync.aligned.m16n8k32.row.col.s32.s8.s8.s32 "
        "{%0,%1,%2,%3}, {%4,%5,%6,%7}, {%8,%9}, {%0,%1,%2,%3};"
        : "+r"(c[0]), "+r"(c[1]), "+r"(c[2]), "+r"(c[3])
        : "r"(a[0]), "r"(a[1]), "r"(a[2]), "r"(a[3]), "r"(b0), "r"(b1));
}
#define CP16(dst, src) asm volatile("cp.async.cg.shared.global [%0], [%1], 16;" :: "r"(dst), "l"(src))
#define CP_COMMIT()    asm volatile("cp.async.commit_group;" ::: "memory")
#define CP_WAIT1()     asm volatile("cp.async.wait_group 1;" ::: "memory")

__device__ __forceinline__ int q8(float v, float inv) {
    int q = __float2int_rn(v * inv);
    return max(-127, min(127, q));
}
__device__ __forceinline__ void top4_ins(float v, int c, float* cv, int* ci) {
    if (v < cv[3]) {
        if (v < cv[2]) {
            cv[3] = cv[2]; ci[3] = ci[2];
            if (v < cv[1]) {
                cv[2] = cv[1]; ci[2] = ci[1];
                if (v < cv[0]) { cv[1] = cv[0]; ci[1] = ci[0]; cv[0] = v; ci[0] = c; }
                else           { cv[1] = v; ci[1] = c; }
            } else { cv[2] = v; ci[2] = c; }
        } else { cv[3] = v; ci[3] = c; }
    }
}

// ---------------- prep kernels ----------------
__global__ void rvq_init_kernel() {
    int t = blockIdx.x * blockDim.x + threadIdx.x;
    if (t < LAYERS) { g_loss[t] = 0.0; g_cmaxb[t] = 0u; g_clomaxb[t] = 0u; g_cabsmax[t] = 0u; }
    for (int i = t; i < LAYERS * KCODES; i += blockDim.x * gridDim.x) g_counts[i] = 0u;
}

// pass 1: per-layer max |c|
__global__ void rvq_prep1_kernel(const float* __restrict__ cb) {
    int w = (blockIdx.x * blockDim.x + threadIdx.x) >> 5;
    int lane = threadIdx.x & 31;
    if (w >= LAYERS * KCODES) return;
    const float* row = cb + (size_t)w * DIM;
    float mx = 0.f;
    #pragma unroll
    for (int j = 0; j < 8; j++) mx = fmaxf(mx, fabsf(row[lane + 32 * j]));
    #pragma unroll
    for (int off = 16; off; off >>= 1) mx = fmaxf(mx, __shfl_down_sync(0xffffffffu, mx, off));
    if (lane == 0) atomicMax(&g_cabsmax[w >> 10], __float_as_uint(mx));
}

// pass 2: quantize codebooks, esq, exact quant-error norms
__global__ void rvq_prep2_kernel(const float* __restrict__ cb) {
    int w = (blockIdx.x * blockDim.x + threadIdx.x) >> 5;
    int lane = threadIdx.x & 31;
    if (w >= LAYERS * KCODES) return;
    const float* row = cb + (size_t)w * DIM;
    char* dst = (char*)g_cbq + (size_t)w * DIM;
    float sc = fmaxf(__uint_as_float(g_cabsmax[w >> 10]), 1e-30f) / 127.f;
    float inv = 1.f / sc;
    double s = 0.0;
    float dq = 0.f;
    #pragma unroll
    for (int j = 0; j < 8; j++) {
        int d = lane + 32 * j;
        float v = row[d];
        s += (double)v * (double)v;
        int q = q8(v, inv);
        dst[d] = (char)q;
        float e = v - sc * (float)q;
        dq += e * e;
    }
    #pragma unroll
    for (int off = 16; off; off >>= 1) {
        s  += __shfl_down_sync(0xffffffffu, s, off);
        dq += __shfl_down_sync(0xffffffffu, dq, off);
    }
    if (lane == 0) {
        g_esq[w] = (float)s;
        atomicMax(&g_cmaxb[w >> 10],   __float_as_uint(sqrtf((float)s)));
        atomicMax(&g_clomaxb[w >> 10], __float_as_uint(sqrtf(dq)));
    }
}

// ---------------- main kernel ----------------
extern __shared__ char smc[];

__global__ __launch_bounds__(THREADS, 2)
void rvq_main_kernel(const float* __restrict__ z,
                     const float* __restrict__ codebooks,
                     float* __restrict__ out)
{
    const int tid  = threadIdx.x;
    const int lane = tid & 31;
    const int wid  = tid >> 5;
    const int wm   = wid & 1;        // 2 warp rows (32 tokens)
    const int wn   = wid >> 1;       // 4 warp cols (32 codes)
    const int m0   = blockIdx.x * TOKB;

    const uint32_t sb = smem_u32p(smc);
    uint32_t* AhU = (uint32_t*)(smc + SM_AH);
    float*  sE    = (float*)(smc + SM_SE);
    float*  sZsq  = (float*)(smc + SM_ZSQ);
    float*  sSr   = (float*)(smc + SM_SR);
    float*  sMar  = (float*)(smc + SM_MAR);
    float*  sGmin = (float*)(smc + SM_GMIN);
    float*  sGm2  = (float*)(smc + SM_GM2);
    int*    sCCnt = (int*)(smc + SM_CCNT);
    int*    sFull = (int*)(smc + SM_FULL);
    unsigned short* sCand = (unsigned short*)(smc + SM_CAND);
    unsigned long long* sBest = (unsigned long long*)(smc + SM_BEST);
    int*    sIdx  = (int*)(smc + SM_IDX);
    int*    sFlag = (int*)(smc + SM_FLAG);
    int*    sNFl  = (int*)(smc + SM_NFL);

    const int g  = lane >> 3, lr = lane & 7;
    const int rofs = lr + (g & 1) * 8;
    const int cofs = (g >> 1) * 16;           // byte offset within k
    const uint32_t aA_base = sb + SM_AH + (uint32_t)(wm * 32 + rofs) * AROWB + cofs;
    // FIX (R11 bug): include the warp-column code offset wn*32
    const uint32_t aB_lane = (uint32_t)(wn * 32 + rofs) * BROW + cofs;

    auto produce = [&](int t) {
        int pl8 = t >> 5, pnc = (t >> 2) & 7, pdc = t & 3;
        const uint4* src = g_cbq + ((size_t)(pl8 * KCODES + pnc * 128) * (DIM / 16)) + pdc * 4;
        uint32_t dst0 = sb + SM_B + (uint32_t)(t % NSTAGE) * BSTAGE;
        #pragma unroll
        for (int i = 0; i < 2; i++) {
            int id = tid + 256 * i;            // 0..511
            int row = id >> 2, c = id & 3;
            CP16(dst0 + (uint32_t)row * BROW + c * 16, src + (size_t)row * (DIM / 16) + c);
        }
    };

    produce(0); CP_COMMIT();
    produce(1); CP_COMMIT();

    const int mtk = tid >> 2, hb = tid & 3;

    // ---- initial: exact zsq/max, then int8-quantize z into A smem ----
    {
        const float4* zrow = (const float4*)(z + (size_t)(m0 + mtk) * DIM + hb * 64);
        float zs = 0.f, mx = 0.f;
        #pragma unroll 8
        for (int j4 = 0; j4 < 16; j4++) {
            float4 v = zrow[j4];
            zs = fmaf(v.x, v.x, zs); zs = fmaf(v.y, v.y, zs);
            zs = fmaf(v.z, v.z, zs); zs = fmaf(v.w, v.w, zs);
            mx = fmaxf(mx, fmaxf(fmaxf(fabsf(v.x), fabsf(v.y)), fmaxf(fabsf(v.z), fabsf(v.w))));
        }
        mx = fmaxf(mx, __shfl_xor_sync(0xffffffffu, mx, 1));
        mx = fmaxf(mx, __shfl_xor_sync(0xffffffffu, mx, 2));
        zs += __shfl_xor_sync(0xffffffffu, zs, 1);
        zs += __shfl_xor_sync(0xffffffffu, zs, 2);
        float sr = fmaxf(mx, 1e-30f) / 127.f;
        float inv = 1.f / sr;
        float d2 = 0.f;
        #pragma unroll 8
        for (int j4 = 0; j4 < 16; j4++) {
            float4 v = zrow[j4];
            int q0 = q8(v.x, inv), q1 = q8(v.y, inv), q2 = q8(v.z, inv), q3 = q8(v.w, inv);
            float e0 = v.x - sr * (float)q0, e1 = v.y - sr * (float)q1;
            float e2 = v.z - sr * (float)q2, e3 = v.w - sr * (float)q3;
            d2 += e0 * e0 + e1 * e1 + e2 * e2 + e3 * e3;
            AhU[mtk * AROWU + hb * 16 + j4] =
                (q0 & 255) | ((q1 & 255) << 8) | ((q2 & 255) << 16) | ((uint32_t)(q3 & 255) << 24);
        }
        d2 += __shfl_xor_sync(0xffffffffu, d2, 1);
        d2 += __shfl_xor_sync(0xffffffffu, d2, 2);
        if ((tid & 3) == 0) {
            sZsq[mtk] = zs; sSr[mtk] = sr;
            float dr = sqrtf(d2);
            float cm = __uint_as_float(g_cmaxb[0]);
            float cl = __uint_as_float(g_clomaxb[0]);
            sMar[mtk] = 4.0f * (dr * cm + (sqrtf(zs) + dr) * cl) + 5e-3f;
        }
    }
    for (int i = tid; i < KCODES; i += THREADS) sE[i] = g_esq[i];
    __syncthreads();

    int tcur = 0;
    for (int lay = 0; lay < LAYERS; lay++) {
        const float* rl = (lay == 0) ? z : g_resid;
        const float sc = fmaxf(__uint_as_float(g_cabsmax[lay]), 1e-30f) / 127.f;

        if (tid < TOKB) { sCCnt[tid] = 0; sFull[tid] = 0; sBest[tid] = ~0ull; }
        if (tid == 0) *sNFl = 0;

        float zq[4], ff[4];
        #pragma unroll
        for (int s = 0; s < 4; s++) {
            int row = wm * 32 + (s >> 1) * 16 + (s & 1) * 8 + (lane >> 2);
            zq[s] = sZsq[row];
            ff[s] = 2.0f * sSr[row] * sc;
        }
        float cv[4][4]; int ci[4][4];
        #pragma unroll
        for (int s = 0; s < 4; s++)
            #pragma unroll
            for (int j = 0; j < 4; j++) { cv[s][j] = 3.4e38f; ci[s][j] = 0; }

        for (int nc = 0; nc < 8; nc++) {
            int acc[2][4][4];
            #pragma unroll
            for (int ma = 0; ma < 2; ma++)
                #pragma unroll
                for (int na = 0; na < 4; na++)
                    #pragma unroll
                    for (int v = 0; v < 4; v++) acc[ma][na][v] = 0;

            for (int dc = 0; dc < 4; dc++) {
                CP_WAIT1();
                __syncthreads();
                if (tcur + 2 < NT_TILES) { produce(tcur + 2); CP_COMMIT(); }
                uint32_t bst = sb + SM_B + (uint32_t)(tcur % NSTAGE) * BSTAGE;
                #pragma unroll
                for (int ks = 0; ks < 2; ks++) {
                    int kB = ks * 32;                     // bytes within tile
                    uint32_t bf[8];
                    #pragma unroll
                    for (int np = 0; np < 2; np++)
                        ldsm_x4(bf + np * 4, bst + aB_lane + (uint32_t)(np * 16) * BROW + kB);
                    uint32_t af[4];
                    #pragma unroll
                    for (int ma = 0; ma < 2; ma++) {
                        ldsm_x4(af, aA_base + (uint32_t)(ma * 16) * AROWB + dc * 64 + kB);
                        #pragma unroll
                        for (int na = 0; na < 4; na++) {
                            int np = na >> 1, o = na & 1;
                            mma_i8(acc[ma][na], af, bf[np * 4 + o], bf[np * 4 + o + 2]);
                        }
                    }
                }
                tcur++;
            }

            // epilogue: dist = (zsq + esq) - f * I  -> per-slot top-4
            #pragma unroll
            for (int na = 0; na < 4; na++) {
                int cbase = nc * 128 + wn * 32 + na * 8 + (lane & 3) * 2;
                float2 e = *(float2*)&sE[cbase];
                #pragma unroll
                for (int ma = 0; ma < 2; ma++) {
                    int* d = acc[ma][na];
                    int s0 = ma * 2, s1 = ma * 2 + 1;
                    float v0 = fmaf(-ff[s0], (float)d[0], zq[s0] + e.x);
                    float v1 = fmaf(-ff[s0], (float)d[1], zq[s0] + e.y);
                    top4_ins(v0, cbase,     cv[s0], ci[s0]);
                    top4_ins(v1, cbase + 1, cv[s0], ci[s0]);
                    float w0 = fmaf(-ff[s1], (float)d[2], zq[s1] + e.x);
                    float w1 = fmaf(-ff[s1], (float)d[3], zq[s1] + e.y);
                    top4_ins(w0, cbase,     cv[s1], ci[s1]);
                    top4_ins(w1, cbase + 1, cv[s1], ci[s1]);
                }
            }
        }

        // global approx min per token
        float gm[4] = {cv[0][0], cv[1][0], cv[2][0], cv[3][0]};
        #pragma unroll
        for (int off = 1; off <= 2; off <<= 1)
            #pragma unroll
            for (int s = 0; s < 4; s++)
                gm[s] = fminf(gm[s], __shfl_xor_sync(0xffffffffu, gm[s], off));
        if ((lane & 3) == 0) {
            #pragma unroll
            for (int s = 0; s < 4; s++) {
                int row = wm * 32 + (s >> 1) * 16 + (s & 1) * 8 + (lane >> 2);
                sGm2[row * 4 + wn] = gm[s];
            }
        }
        __syncthreads();
        if (tid < TOKB)
            sGmin[tid] = fminf(fminf(sGm2[4 * tid], sGm2[4 * tid + 1]),
                               fminf(sGm2[4 * tid + 2], sGm2[4 * tid + 3]));
        __syncthreads();

        // candidate filter (rigorous quantization margin) + completeness check
        #pragma unroll
        for (int s = 0; s < 4; s++) {
            int row = wm * 32 + (s >> 1) * 16 + (s & 1) * 8 + (lane >> 2);
            float thr = sGmin[row] + sMar[row];
            if (cv[s][3] <= thr) sFull[row] = 1;
            #pragma unroll
            for (int j = 0; j < 4; j++) {
                if (cv[s][j] <= thr) {
                    int pos = atomicAdd(&sCCnt[row], 1);   // provably <= 64
                    sCand[row * 64 + pos] = (unsigned short)ci[s][j];
                }
            }
        }
        __syncthreads();
        if (tid < TOKB && sFull[tid]) { int p = atomicAdd(sNFl, 1); sFlag[p] = tid; }
        __syncthreads();

        // exact fp32 scoring of candidates (serial ascending fma; exact residual)
        {
            int tok = tid >> 2, sub = tid & 3;
            if (!sFull[tok]) {
                int cnt = sCCnt[tok];
                float zqs = sZsq[tok];
                const float4* rrow4 = (const float4*)(rl + (size_t)(m0 + tok) * DIM);
                for (int j = sub; j < cnt; j += 4) {
                    int c = sCand[tok * 64 + j];
                    const float4* crow = (const float4*)(codebooks +
                        ((size_t)lay * KCODES + c) * DIM);
                    float dot = 0.f;
                    #pragma unroll 8
                    for (int q4 = 0; q4 < 64; q4++) {
                        float4 cvv = crow[q4]; float4 rv = rrow4[q4];
                        dot = fmaf(rv.x, cvv.x, dot); dot = fmaf(rv.y, cvv.y, dot);
                        dot = fmaf(rv.z, cvv.z, dot); dot = fmaf(rv.w, cvv.w, dot);
                    }
                    float dist = fmaf(-2.0f, dot, zqs + sE[c]);
                    unsigned long long pk =
                        ((unsigned long long)__float_as_uint(dist) << 32) | (unsigned)c;
                    atomicMin(&sBest[tok], pk);
                }
            }
        }
        // rare fallback: full 1024-code exact rescan
        {
            int nf = *sNFl;
            for (int f = 0; f < nf; f++) {
                int tok = sFlag[f];
                float zqs = sZsq[tok];
                const float4* rrow4 = (const float4*)(rl + (size_t)(m0 + tok) * DIM);
                #pragma unroll
                for (int j = 0; j < 4; j++) {
                    int c = tid + 256 * j;
                    const float4* crow = (const float4*)(codebooks +
                        ((size_t)lay * KCODES + c) * DIM);
                    float dot = 0.f;
                    #pragma unroll 8
                    for (int q4 = 0; q4 < 64; q4++) {
                        float4 cvv = crow[q4]; float4 rv = rrow4[q4];
                        dot = fmaf(rv.x, cvv.x, dot); dot = fmaf(rv.y, cvv.y, dot);
                        dot = fmaf(rv.z, cvv.z, dot); dot = fmaf(rv.w, cvv.w, dot);
                    }
                    float dist = fmaf(-2.0f, dot, zqs + sE[c]);
                    unsigned long long pk =
                        ((unsigned long long)__float_as_uint(dist) << 32) | (unsigned)c;
                    atomicMin(&sBest[tok], pk);
                }
            }
        }
        __syncthreads();

        if (tid < TOKB) {
            int idx = (int)(sBest[tid] & 0xFFFFFFFFull);
            sIdx[tid] = idx;
            out[(size_t)N_TOK * DIM + (size_t)lay * N_TOK + m0 + tid] = (float)idx;
            atomicAdd(&g_counts[lay * KCODES + idx], 1u);
        }
        __syncthreads();

        // update from EXACT residual; write exact chain + fresh int8 quantization
        {
            int idx = sIdx[mtk];
            size_t tok = (size_t)(m0 + mtk);
            const float4* crow = (const float4*)(codebooks +
                ((size_t)lay * KCODES + idx) * DIM + hb * 64);
            const float4* rrow = (const float4*)(rl + tok * DIM + hb * 64);
            float lss = 0.f;
            if (lay < 7) {
                float4* wrow = (float4*)(g_resid + tok * DIM + hb * 64);
                float zs = 0.f, mx = 0.f;
                #pragma unroll 4
                for (int j4 = 0; j4 < 16; j4++) {
                    float4 q = crow[j4];
                    float4 r = rrow[j4];
                    float d0 = r.x - q.x, d1 = r.y - q.y, d2 = r.z - q.z, d3 = r.w - q.w;
                    lss = fmaf(d0, d0, lss); lss = fmaf(d1, d1, lss);
                    lss = fmaf(d2, d2, lss); lss = fmaf(d3, d3, lss);
                    float n0 = r.x - (r.x + (q.x - r.x));
                    float n1 = r.y - (r.y + (q.y - r.y));
                    float n2 = r.z - (r.z + (q.z - r.z));
                    float n3 = r.w - (r.w + (q.w - r.w));
                    zs = fmaf(n0, n0, zs); zs = fmaf(n1, n1, zs);
                    zs = fmaf(n2, n2, zs); zs = fmaf(n3, n3, zs);
                    mx = fmaxf(mx, fmaxf(fmaxf(fabsf(n0), fabsf(n1)), fmaxf(fabsf(n2), fabsf(n3))));
                    float4 nw; nw.x = n0; nw.y = n1; nw.z = n2; nw.w = n3;
                    wrow[j4] = nw;
                }
                mx = fmaxf(mx, __shfl_xor_sync(0xffffffffu, mx, 1));
                mx = fmaxf(mx, __shfl_xor_sync(0xffffffffu, mx, 2));
                zs += __shfl_xor_sync(0xffffffffu, zs, 1);
                zs += __shfl_xor_sync(0xffffffffu, zs, 2);
                float sr = fmaxf(mx, 1e-30f) / 127.f;
                float inv = 1.f / sr;
                float d2s = 0.f;
                #pragma unroll 4
                for (int j4 = 0; j4 < 16; j4++) {
                    float4 n = wrow[j4];
                    int q0 = q8(n.x, inv), q1 = q8(n.y, inv), q2 = q8(n.z, inv), q3 = q8(n.w, inv);
                    float e0 = n.x - sr * (float)q0, e1 = n.y - sr * (float)q1;
                    float e2 = n.z - sr * (float)q2, e3 = n.w - sr * (float)q3;
                    d2s += e0 * e0 + e1 * e1 + e2 * e2 + e3 * e3;
                    AhU[mtk * AROWU + hb * 16 + j4] =
                        (q0 & 255) | ((q1 & 255) << 8) | ((q2 & 255) << 16) | ((uint32_t)(q3 & 255) << 24);
                }
                d2s += __shfl_xor_sync(0xffffffffu, d2s, 1);
                d2s += __shfl_xor_sync(0xffffffffu, d2s, 2);
                if ((tid & 3) == 0) {
                    sZsq[mtk] = zs; sSr[mtk] = sr;
                    float dr = sqrtf(d2s);
                    float cm = __uint_as_float(g_cmaxb[lay + 1]);
                    float cl = __uint_as_float(g_clomaxb[lay + 1]);
                    sMar[mtk] = 4.0f * (dr * cm + (sqrtf(zs) + dr) * cl) + 5e-3f;
                }
            } else {
                const float4* zrow = (const float4*)(z + tok * DIM + hb * 64);
                float4* orow = (float4*)(out + tok * DIM + hb * 64);
                #pragma unroll 4
                for (int j4 = 0; j4 < 16; j4++) {
                    float4 q = crow[j4];
                    float4 r = rrow[j4];
                    float d0 = r.x - q.x, d1 = r.y - q.y, d2 = r.z - q.z, d3 = r.w - q.w;
                    lss = fmaf(d0, d0, lss); lss = fmaf(d1, d1, lss);
                    lss = fmaf(d2, d2, lss); lss = fmaf(d3, d3, lss);
                    float n0 = r.x - (r.x + (q.x - r.x));
                    float n1 = r.y - (r.y + (q.y - r.y));
                    float n2 = r.z - (r.z + (q.z - r.z));
                    float n3 = r.w - (r.w + (q.w - r.w));
                    float4 zv = zrow[j4];
                    float4 ov;
                    ov.x = zv.x - n0; ov.y = zv.y - n1; ov.z = zv.z - n2; ov.w = zv.w - n3;
                    orow[j4] = ov;
                }
            }
            #pragma unroll
            for (int off = 16; off; off >>= 1)
                lss += __shfl_down_sync(0xffffffffu, lss, off);
            if (lane == 0) atomicAdd(&g_loss[lay], (double)lss);
        }
        __syncthreads();
        if (lay < 7) {
            for (int i = tid; i < KCODES; i += THREADS) sE[i] = g_esq[(lay + 1) * KCODES + i];
            __syncthreads();
        }
    }
}

// ---------------- finalize ----------------
__global__ void rvq_final_kernel(float* __restrict__ out) {
    __shared__ double red[8];
    int t = threadIdx.x;
    double total_perp = 0.0;
    for (int l = 0; l < LAYERS; l++) {
        double local = 0.0;
        for (int k = t; k < KCODES; k += 256) {
            float p = (float)g_counts[l * KCODES + k] / (float)N_TOK;
            local += (double)(p * logf(p + 1e-10f));
        }
        #pragma unroll
        for (int off = 16; off; off >>= 1)
            local += __shfl_down_sync(0xffffffffu, local, off);
        if ((t & 31) == 0) red[t >> 5] = local;
        __syncthreads();
        if (t == 0) {
            double s = 0.0;
            for (int w = 0; w < 8; w++) s += red[w];
            total_perp += exp(-s);
        }
        __syncthreads();
    }
    if (t == 0) {
        double tc = 0.0;
        for (int l = 0; l < LAYERS; l++)
            tc += g_loss[l] / ((double)N_TOK * (double)DIM);
        size_t off = (size_t)N_TOK * DIM + (size_t)LAYERS * N_TOK;
        out[off + 0] = (float)(0.25 * tc + tc);
        out[off + 1] = (float)tc;
        out[off + 2] = (float)tc;
        out[off + 3] = (float)(total_perp / (double)LAYERS);
    }
}

// ---------------- launch ----------------
extern "C" void kernel_launch(void* const* d_in, const int* in_sizes, int n_in,
                              void* d_out, int out_size) {
    const float* z  = (const float*)d_in[0];
    const float* cb = (const float*)d_in[1];
    float* out = (float*)d_out;

    cudaFuncSetAttribute(rvq_main_kernel,
                         cudaFuncAttributeMaxDynamicSharedMemorySize, SM_TOTAL);

    rvq_init_kernel<<<1, 256>>>();
    rvq_prep1_kernel<<<(LAYERS * KCODES * 32 + 255) / 256, 256>>>(cb);
    rvq_prep2_kernel<<<(LAYERS * KCODES * 32 + 255) / 256, 256>>>(cb);
    rvq_main_kernel<<<N_TOK / TOKB, THREADS, SM_TOTAL>>>(z, cb, out);
    rvq_final_kernel<<<1, 256>>>(out);
}

// round 13
// speedup vs baseline: 1.1531x; 1.1531x over previous
#include <cuda_runtime.h>
#include <cuda_bf16.h>
#include <math.h>
#include <stdint.h>

#define N_TOK   65536
#define DIM     256
#define KCODES  1024
#define LAYERS  8
#define THREADS 256
#define TOKB    64            // tokens per CTA
#define NT_TILES 256          // 8 layers * 8 nchunks * 4 dchunks (hi split only)
#define BROW    144           // B smem row bytes: 64 dims*2B + 16B pad
#define BSTAGE  (128*BROW)    // 18432 B per stage
#define NSTAGE  3
#define AROW    528           // A smem row bytes: 264 bf16 (256 + 8 pad)
#define AROWU   132           // A row stride in u32

// smem byte offsets
#define SM_AH    0
#define SM_B     (SM_AH + TOKB*AROW)          // 33792
#define SM_SE    (SM_B + NSTAGE*BSTAGE)       // 89088
#define SM_ZSQ   (SM_SE + 4096)               // 93184
#define SM_PART  (SM_ZSQ + 256)               // 93440
#define SM_PART2 (SM_PART + 1024)             // 94464
#define SM_MAR   (SM_PART2 + 1024)            // 95488
#define SM_GMIN  (SM_MAR + 256)               // 95744
#define SM_GM2   (SM_GMIN + 256)              // 96000  f32[64][4]
#define SM_CCNT  (SM_GM2 + 1024)              // 97024
#define SM_FULL  (SM_CCNT + 256)              // 97280
#define SM_CAND  (SM_FULL + 256)              // 97536  u16[64][64]
#define SM_BEST  (SM_CAND + 8192)             // 105728 u64[64]
#define SM_IDX   (SM_BEST + 512)              // 106240
#define SM_FLAG  (SM_IDX + 256)               // 106496
#define SM_NFL   (SM_FLAG + 256)              // 106752
#define SM_TOTAL (SM_NFL + 16)                // 106768

// ---------------- device globals ----------------
__device__ double        g_loss[LAYERS];
__device__ unsigned int  g_counts[LAYERS * KCODES];
__device__ float         g_esq[LAYERS * KCODES];
__device__ unsigned int  g_cmaxb[LAYERS];
__device__ unsigned int  g_clomaxb[LAYERS];
__device__ __nv_bfloat16 g_cbh[LAYERS * KCODES * DIM];
__device__ float         g_resid[(size_t)N_TOK * DIM];   // EXACT fp32 residual chain

// ---------------- helpers ----------------
__device__ __forceinline__ uint32_t smem_u32p(const void* p) {
    uint32_t a;
    asm("{ .reg .u64 t; cvta.to.shared.u64 t, %1; cvt.u32.u64 %0, t; }" : "=r"(a) : "l"(p));
    return a;
}
__device__ __forceinline__ float ulo(uint32_t u) { return __uint_as_float(u << 16); }
__device__ __forceinline__ float uhi(uint32_t u) { return __uint_as_float(u & 0xffff0000u); }
// packed rn conversion: lo = v0, hi = v1 (identical rounding to __float2bfloat16)
__device__ __forceinline__ uint32_t cvt2bf(float v0, float v1) {
    uint32_t r;
    asm("cvt.rn.satfinite.bf16x2.f32 %0, %1, %2;" : "=r"(r) : "f"(v1), "f"(v0));
    return r;
}
// hi bf16 pair (packed) + fp32 remainders
__device__ __forceinline__ uint32_t splithi(float v0, float v1, float& r0, float& r1) {
    uint32_t h = cvt2bf(v0, v1);
    r0 = v0 - ulo(h); r1 = v1 - uhi(h);
    return h;
}

__device__ __forceinline__ void ldsm_x4(uint32_t* r, uint32_t addr) {
    asm volatile("ldmatrix.sync.aligned.m8n8.x4.shared.b16 {%0,%1,%2,%3}, [%4];"
        : "=r"(r[0]), "=r"(r[1]), "=r"(r[2]), "=r"(r[3]) : "r"(addr));
}
__device__ __forceinline__ void mma16816(float* c, const uint32_t* a, uint32_t b0, uint32_t b1) {
    asm volatile("mma.sync.aligned.m16n8k16.row.col.f32.bf16.bf16.f32 "
        "{%0,%1,%2,%3}, {%4,%5,%6,%7}, {%8,%9}, {%0,%1,%2,%3};"
        : "+f"(c[0]), "+f"(c[1]), "+f"(c[2]), "+f"(c[3])
        : "r"(a[0]), "r"(a[1]), "r"(a[2]), "r"(a[3]), "r"(b0), "r"(b1));
}
#define CP16(dst, src) asm volatile("cp.async.cg.shared.global [%0], [%1], 16;" :: "r"(dst), "l"(src))
#define CP_COMMIT()    asm volatile("cp.async.commit_group;" ::: "memory")
#define CP_WAIT1()     asm volatile("cp.async.wait_group 1;" ::: "memory")

__device__ __forceinline__ void top4_ins(float v, int c, float* cv, int* ci) {
    if (v < cv[3]) {
        if (v < cv[2]) {
            cv[3] = cv[2]; ci[3] = ci[2];
            if (v < cv[1]) {
                cv[2] = cv[1]; ci[2] = ci[1];
                if (v < cv[0]) { cv[1] = cv[0]; ci[1] = ci[0]; cv[0] = v; ci[0] = c; }
                else           { cv[1] = v; ci[1] = c; }
            } else { cv[2] = v; ci[2] = c; }
        } else { cv[3] = v; ci[3] = c; }
    }
}

// ---------------- prep kernels ----------------
__global__ void rvq_init_kernel() {
    int t = blockIdx.x * blockDim.x + threadIdx.x;
    if (t < LAYERS) { g_loss[t] = 0.0; g_cmaxb[t] = 0u; g_clomaxb[t] = 0u; }
    for (int i = t; i < LAYERS * KCODES; i += blockDim.x * gridDim.x) g_counts[i] = 0u;
}

__global__ void rvq_prep_kernel(const float* __restrict__ cb) {
    int w = (blockIdx.x * blockDim.x + threadIdx.x) >> 5;
    int lane = threadIdx.x & 31;
    if (w >= LAYERS * KCODES) return;
    const float* row = cb + (size_t)w * DIM;
    __nv_bfloat16* ph = g_cbh + (size_t)w * DIM;
    double s = 0.0;
    float slo = 0.f;
    #pragma unroll
    for (int j = 0; j < 8; j++) {
        int d = lane + 32 * j;
        float v = row[d];
        s += (double)v * (double)v;
        __nv_bfloat16 hb = __float2bfloat16(v);
        ph[d] = hb;
        float lo = v - __bfloat162float(hb);
        slo += lo * lo;
    }
    #pragma unroll
    for (int off = 16; off; off >>= 1) {
        s   += __shfl_down_sync(0xffffffffu, s, off);
        slo += __shfl_down_sync(0xffffffffu, slo, off);
    }
    if (lane == 0) {
        g_esq[w] = (float)s;
        atomicMax(&g_cmaxb[w >> 10],   __float_as_uint(sqrtf((float)s)));
        atomicMax(&g_clomaxb[w >> 10], __float_as_uint(sqrtf(slo)));
    }
}

// ---------------- main kernel ----------------
extern __shared__ char smc[];

__global__ __launch_bounds__(THREADS, 2)
void rvq_main_kernel(const float* __restrict__ z,
                     const float* __restrict__ codebooks,
                     float* __restrict__ out)
{
    const int tid  = threadIdx.x;
    const int lane = tid & 31;
    const int wid  = tid >> 5;
    const int wm   = wid & 1;        // 2 warp rows (32 tokens each)
    const int wn   = wid >> 1;       // 4 warp cols (32 codes each)
    const int m0   = blockIdx.x * TOKB;

    const uint32_t sb = smem_u32p(smc);
    uint32_t* AhU = (uint32_t*)(smc + SM_AH);
    float*  sE    = (float*)(smc + SM_SE);
    float*  sZsq  = (float*)(smc + SM_ZSQ);
    float*  sPart = (float*)(smc + SM_PART);
    float*  sPart2= (float*)(smc + SM_PART2);
    float*  sMar  = (float*)(smc + SM_MAR);
    float*  sGmin = (float*)(smc + SM_GMIN);
    float*  sGm2  = (float*)(smc + SM_GM2);
    int*    sCCnt = (int*)(smc + SM_CCNT);
    int*    sFull = (int*)(smc + SM_FULL);
    unsigned short* sCand = (unsigned short*)(smc + SM_CAND);
    unsigned long long* sBest = (unsigned long long*)(smc + SM_BEST);
    int*    sIdx  = (int*)(smc + SM_IDX);
    int*    sFlag = (int*)(smc + SM_FLAG);
    int*    sNFl  = (int*)(smc + SM_NFL);

    const int g  = lane >> 3, lr = lane & 7;
    const int rofs = lr + (g & 1) * 8;
    const int kofs = (g >> 1) * 8;
    const uint32_t aA_base = sb + SM_AH + (uint32_t)(wm * 32 + rofs) * AROW + kofs * 2;
    const uint32_t aB_lane = (uint32_t)(wn * 32 + rofs) * BROW + kofs * 2;

    auto produce = [&](int t) {
        int pl8 = t >> 5, pnc = (t >> 2) & 7, pdc = t & 3;
        const __nv_bfloat16* src0 = g_cbh + ((size_t)(pl8 * KCODES + pnc * 128) * DIM) + pdc * 64;
        uint32_t dst0 = sb + SM_B + (uint32_t)(t % NSTAGE) * BSTAGE;
        #pragma unroll
        for (int i = 0; i < 4; i++) {
            int id = tid + 256 * i;
            int row = id >> 3, c = id & 7;
            CP16(dst0 + (uint32_t)row * BROW + c * 16, src0 + (size_t)row * DIM + c * 8);
        }
    };

    produce(0); CP_COMMIT();
    produce(1); CP_COMMIT();

    // split z (hi into smem A), exact zsq + lo-norm partials (4 threads/token)
    {
        int mtk = tid >> 2, hb = tid & 3;
        const float4* zrow = (const float4*)(z + (size_t)(m0 + mtk) * DIM + hb * 64);
        float zs = 0.f, l2 = 0.f;
        #pragma unroll 8
        for (int j4 = 0; j4 < 16; j4++) {
            float4 v = zrow[j4];
            zs = fmaf(v.x, v.x, zs); zs = fmaf(v.y, v.y, zs);
            zs = fmaf(v.z, v.z, zs); zs = fmaf(v.w, v.w, zs);
            float e0, e1, e2, e3;
            uint32_t h0 = splithi(v.x, v.y, e0, e1);
            uint32_t h1 = splithi(v.z, v.w, e2, e3);
            l2 += e0 * e0 + e1 * e1 + e2 * e2 + e3 * e3;
            uint32_t pa = (uint32_t)mtk * AROWU + hb * 32 + j4 * 2;
            AhU[pa] = h0; AhU[pa + 1] = h1;
        }
        sPart[tid] = zs; sPart2[tid] = l2;
    }
    for (int i = tid; i < KCODES; i += THREADS) sE[i] = g_esq[i];
    __syncthreads();
    if (tid < TOKB) {
        float zs = (sPart[4 * tid] + sPart[4 * tid + 1]) + (sPart[4 * tid + 2] + sPart[4 * tid + 3]);
        float l2 = (sPart2[4 * tid] + sPart2[4 * tid + 1]) + (sPart2[4 * tid + 2] + sPart2[4 * tid + 3]);
        float la = sqrtf(l2);
        sZsq[tid] = zs;
        float cm = __uint_as_float(g_cmaxb[0]);
        float cl = __uint_as_float(g_clomaxb[0]);
        sMar[tid] = 4.0f * (la * cm + (sqrtf(zs) + la) * cl) + 5e-3f;
    }
    __syncthreads();

    int tcur = 0;
    for (int lay = 0; lay < LAYERS; lay++) {
        const float* rl = (lay == 0) ? z : g_resid;

        if (tid < TOKB) { sCCnt[tid] = 0; sFull[tid] = 0; sBest[tid] = ~0ull; }
        if (tid == 0) *sNFl = 0;

        float zq[4];
        #pragma unroll
        for (int s = 0; s < 4; s++)
            zq[s] = sZsq[wm * 32 + (s >> 1) * 16 + (s & 1) * 8 + (lane >> 2)];
        float cv[4][4]; int ci[4][4];
        #pragma unroll
        for (int s = 0; s < 4; s++)
            #pragma unroll
            for (int j = 0; j < 4; j++) { cv[s][j] = 3.4e38f; ci[s][j] = 0; }

        for (int nc = 0; nc < 8; nc++) {
            float acc[2][4][4];
            #pragma unroll
            for (int ma = 0; ma < 2; ma++)
                #pragma unroll
                for (int na = 0; na < 4; na++)
                    #pragma unroll
                    for (int v = 0; v < 4; v++) acc[ma][na][v] = 0.f;

            for (int dc = 0; dc < 4; dc++) {
                CP_WAIT1();
                __syncthreads();
                if (tcur + 2 < NT_TILES) { produce(tcur + 2); CP_COMMIT(); }
                uint32_t bst = sb + SM_B + (uint32_t)(tcur % NSTAGE) * BSTAGE;
                #pragma unroll
                for (int ks = 0; ks < 4; ks++) {
                    int k0 = ks * 16, kA = dc * 64 + k0;
                    uint32_t bf[8];
                    #pragma unroll
                    for (int np = 0; np < 2; np++)
                        ldsm_x4(bf + np * 4, bst + aB_lane + (uint32_t)(np * 16) * BROW + k0 * 2);
                    uint32_t af[4];
                    #pragma unroll
                    for (int ma = 0; ma < 2; ma++) {
                        ldsm_x4(af, aA_base + (uint32_t)(ma * 16) * AROW + kA * 2);
                        #pragma unroll
                        for (int na = 0; na < 4; na++) {
                            int np = na >> 1, o = na & 1;
                            mma16816(acc[ma][na], af, bf[np * 4 + o], bf[np * 4 + o + 2]);
                        }
                    }
                }
                tcur++;
            }

            // epilogue: approx distances -> per-slot top-4
            #pragma unroll
            for (int na = 0; na < 4; na++) {
                int cbase = nc * 128 + wn * 32 + na * 8 + (lane & 3) * 2;
                float2 e = *(float2*)&sE[cbase];
                #pragma unroll
                for (int ma = 0; ma < 2; ma++) {
                    float* d = acc[ma][na];
                    int s0 = ma * 2, s1 = ma * 2 + 1;
                    float v0 = fmaf(-2.0f, d[0], zq[s0] + e.x);
                    float v1 = fmaf(-2.0f, d[1], zq[s0] + e.y);
                    top4_ins(v0, cbase,     cv[s0], ci[s0]);
                    top4_ins(v1, cbase + 1, cv[s0], ci[s0]);
                    float w0 = fmaf(-2.0f, d[2], zq[s1] + e.x);
                    float w1 = fmaf(-2.0f, d[3], zq[s1] + e.y);
                    top4_ins(w0, cbase,     cv[s1], ci[s1]);
                    top4_ins(w1, cbase + 1, cv[s1], ci[s1]);
                }
            }
        }

        // global approx min per token (4 lanes share a row, then 4 wn)
        float gm[4] = {cv[0][0], cv[1][0], cv[2][0], cv[3][0]};
        #pragma unroll
        for (int off = 1; off <= 2; off <<= 1)
            #pragma unroll
            for (int s = 0; s < 4; s++)
                gm[s] = fminf(gm[s], __shfl_xor_sync(0xffffffffu, gm[s], off));
        if ((lane & 3) == 0) {
            #pragma unroll
            for (int s = 0; s < 4; s++) {
                int row = wm * 32 + (s >> 1) * 16 + (s & 1) * 8 + (lane >> 2);
                sGm2[row * 4 + wn] = gm[s];
            }
        }
        __syncthreads();
        if (tid < TOKB)
            sGmin[tid] = fminf(fminf(sGm2[4 * tid], sGm2[4 * tid + 1]),
                               fminf(sGm2[4 * tid + 2], sGm2[4 * tid + 3]));
        __syncthreads();

        // candidate filter (rigorous margin) + completeness check
        #pragma unroll
        for (int s = 0; s < 4; s++) {
            int row = wm * 32 + (s >> 1) * 16 + (s & 1) * 8 + (lane >> 2);
            float thr = sGmin[row] + sMar[row];
            if (cv[s][3] <= thr) sFull[row] = 1;
            #pragma unroll
            for (int j = 0; j < 4; j++) {
                if (cv[s][j] <= thr) {
                    int pos = atomicAdd(&sCCnt[row], 1);
                    sCand[row * 64 + pos] = (unsigned short)ci[s][j];
                }
            }
        }
        __syncthreads();
        if (tid < TOKB && sFull[tid]) { int p = atomicAdd(sNFl, 1); sFlag[p] = tid; }
        __syncthreads();

        // exact fp32 scoring of candidates (serial ascending fma; exact residual)
        {
            int tok = tid >> 2, sub = tid & 3;
            if (!sFull[tok]) {
                int cnt = sCCnt[tok];
                float zqs = sZsq[tok];
                const float4* rrow4 = (const float4*)(rl + (size_t)(m0 + tok) * DIM);
                for (int j = sub; j < cnt; j += 4) {
                    int c = sCand[tok * 64 + j];
                    const float4* crow = (const float4*)(codebooks +
                        ((size_t)lay * KCODES + c) * DIM);
                    float dot = 0.f;
                    #pragma unroll 8
                    for (int q4 = 0; q4 < 64; q4++) {
                        float4 cvv = crow[q4]; float4 rv = rrow4[q4];
                        dot = fmaf(rv.x, cvv.x, dot); dot = fmaf(rv.y, cvv.y, dot);
                        dot = fmaf(rv.z, cvv.z, dot); dot = fmaf(rv.w, cvv.w, dot);
                    }
                    float dist = fmaf(-2.0f, dot, zqs + sE[c]);
                    unsigned long long pk =
                        ((unsigned long long)__float_as_uint(dist) << 32) | (unsigned)c;
                    atomicMin(&sBest[tok], pk);
                }
            }
        }
        // rare fallback: full 1024-code exact rescan
        {
            int nf = *sNFl;
            for (int f = 0; f < nf; f++) {
                int tok = sFlag[f];
                float zqs = sZsq[tok];
                const float4* rrow4 = (const float4*)(rl + (size_t)(m0 + tok) * DIM);
                #pragma unroll
                for (int j = 0; j < 4; j++) {
                    int c = tid + 256 * j;
                    const float4* crow = (const float4*)(codebooks +
                        ((size_t)lay * KCODES + c) * DIM);
                    float dot = 0.f;
                    #pragma unroll 8
                    for (int q4 = 0; q4 < 64; q4++) {
                        float4 cvv = crow[q4]; float4 rv = rrow4[q4];
                        dot = fmaf(rv.x, cvv.x, dot); dot = fmaf(rv.y, cvv.y, dot);
                        dot = fmaf(rv.z, cvv.z, dot); dot = fmaf(rv.w, cvv.w, dot);
                    }
                    float dist = fmaf(-2.0f, dot, zqs + sE[c]);
                    unsigned long long pk =
                        ((unsigned long long)__float_as_uint(dist) << 32) | (unsigned)c;
                    atomicMin(&sBest[tok], pk);
                }
            }
        }
        __syncthreads();

        if (tid < TOKB) {
            int idx = (int)(sBest[tid] & 0xFFFFFFFFull);
            sIdx[tid] = idx;
            out[(size_t)N_TOK * DIM + (size_t)lay * N_TOK + m0 + tid] = (float)idx;
            atomicAdd(&g_counts[lay * KCODES + idx], 1u);
        }
        __syncthreads();

        // update from EXACT residual; write exact chain + fresh hi split
        {
            int mtk = tid >> 2, hb = tid & 3;
            int idx = sIdx[mtk];
            size_t tok = (size_t)(m0 + mtk);
            const float4* crow = (const float4*)(codebooks +
                ((size_t)lay * KCODES + idx) * DIM + hb * 64);
            const float4* rrow = (const float4*)(rl + tok * DIM + hb * 64);
            float4* wrow = (float4*)(g_resid + tok * DIM + hb * 64);
            const float4* zrow = (const float4*)(z + tok * DIM + hb * 64);
            float4* orow = (float4*)(out + tok * DIM + hb * 64);
            float lss = 0.f, zs = 0.f, l2 = 0.f;
            #pragma unroll 4
            for (int j4 = 0; j4 < 16; j4++) {
                float4 q = crow[j4];
                float4 r = rrow[j4];
                float d0 = r.x - q.x, d1 = r.y - q.y, d2 = r.z - q.z, d3 = r.w - q.w;
                lss = fmaf(d0, d0, lss); lss = fmaf(d1, d1, lss);
                lss = fmaf(d2, d2, lss); lss = fmaf(d3, d3, lss);
                float n0 = r.x - (r.x + (q.x - r.x));
                float n1 = r.y - (r.y + (q.y - r.y));
                float n2 = r.z - (r.z + (q.z - r.z));
                float n3 = r.w - (r.w + (q.w - r.w));
                if (lay < 7) {
                    zs = fmaf(n0, n0, zs); zs = fmaf(n1, n1, zs);
                    zs = fmaf(n2, n2, zs); zs = fmaf(n3, n3, zs);
                    float4 nw; nw.x = n0; nw.y = n1; nw.z = n2; nw.w = n3;
                    wrow[j4] = nw;
                    float e0, e1, e2, e3;
                    uint32_t h0 = splithi(n0, n1, e0, e1);
                    uint32_t h1 = splithi(n2, n3, e2, e3);
                    l2 += e0 * e0 + e1 * e1 + e2 * e2 + e3 * e3;
                    uint32_t pa = (uint32_t)mtk * AROWU + hb * 32 + j4 * 2;
                    AhU[pa] = h0; AhU[pa + 1] = h1;
                } else {
                    float4 zv = zrow[j4];
                    float4 ov;
                    ov.x = zv.x - n0; ov.y = zv.y - n1; ov.z = zv.z - n2; ov.w = zv.w - n3;
                    orow[j4] = ov;
                }
            }
            sPart[tid] = zs; sPart2[tid] = l2;
            #pragma unroll
            for (int off = 16; off; off >>= 1)
                lss += __shfl_down_sync(0xffffffffu, lss, off);
            if (lane == 0) atomicAdd(&g_loss[lay], (double)lss);
        }
        __syncthreads();
        if (lay < 7) {
            if (tid < TOKB) {
                float zs = (sPart[4 * tid] + sPart[4 * tid + 1]) + (sPart[4 * tid + 2] + sPart[4 * tid + 3]);
                float l2 = (sPart2[4 * tid] + sPart2[4 * tid + 1]) + (sPart2[4 * tid + 2] + sPart2[4 * tid + 3]);
                float la = sqrtf(l2);
                sZsq[tid] = zs;
                float cm = __uint_as_float(g_cmaxb[lay + 1]);
                float cl = __uint_as_float(g_clomaxb[lay + 1]);
                sMar[tid] = 4.0f * (la * cm + (sqrtf(zs) + la) * cl) + 5e-3f;
            }
            for (int i = tid; i < KCODES; i += THREADS) sE[i] = g_esq[(lay + 1) * KCODES + i];
            __syncthreads();
        }
    }
}

// ---------------- finalize ----------------
__global__ void rvq_final_kernel(float* __restrict__ out) {
    __shared__ double red[8];
    int t = threadIdx.x;
    double total_perp = 0.0;
    for (int l = 0; l < LAYERS; l++) {
        double local = 0.0;
        for (int k = t; k < KCODES; k += 256) {
            float p = (float)g_counts[l * KCODES + k] / (float)N_TOK;
            local += (double)(p * logf(p + 1e-10f));
        }
        #pragma unroll
        for (int off = 16; off; off >>= 1)
            local += __shfl_down_sync(0xffffffffu, local, off);
        if ((t & 31) == 0) red[t >> 5] = local;
        __syncthreads();
        if (t == 0) {
            double s = 0.0;
            for (int w = 0; w < 8; w++) s += red[w];
            total_perp += exp(-s);
        }
        __syncthreads();
    }
    if (t == 0) {
        double tc = 0.0;
        for (int l = 0; l < LAYERS; l++)
            tc += g_loss[l] / ((double)N_TOK * (double)DIM);
        size_t off = (size_t)N_TOK * DIM + (size_t)LAYERS * N_TOK;
        out[off + 0] = (float)(0.25 * tc + tc);
        out[off + 1] = (float)tc;
        out[off + 2] = (float)tc;
        out[off + 3] = (float)(total_perp / (double)LAYERS);
    }
}

// ---------------- launch ----------------
extern "C" void kernel_launch(void* const* d_in, const int* in_sizes, int n_in,
                              void* d_out, int out_size) {
    const float* z  = (const float*)d_in[0];
    const float* cb = (const float*)d_in[1];
    float* out = (float*)d_out;

    cudaFuncSetAttribute(rvq_main_kernel,
                         cudaFuncAttributeMaxDynamicSharedMemorySize, SM_TOTAL);

    rvq_init_kernel<<<1, 256>>>();
    rvq_prep_kernel<<<(LAYERS * KCODES * 32 + 255) / 256, 256>>>(cb);
    rvq_main_kernel<<<N_TOK / TOKB, THREADS, SM_TOTAL>>>(z, cb, out);
    rvq_final_kernel<<<1, 256>>>(out);
}